// round 5
// baseline (speedup 1.0000x reference)
#include <cuda_runtime.h>
#include <cuda_fp16.h>
#include <cstdint>

// Problem dims
#define N_TOK 8192
#define H_DIM 4096
#define V_DIM 32000
// Tiling (int8: BK = 64 bytes per K-iter)
#define BM 128
#define BN 256
#define BK 64
#define KITERS (H_DIM / BK)   // 64
#define NVB (V_DIM / BN)      // 125
#define NRB (N_TOK / BM)      // 64
#define STAGE_BYTES 24576     // A 8KB + B 16KB
#define NSTAGE 3
#define SMEM_TOTAL (STAGE_BYTES * NSTAGE)   // 73728

// Scratch (static __device__ arrays: allocation-free per harness rules)
__device__ signed char g_A[(size_t)N_TOK * H_DIM];     // 32 MB
__device__ signed char g_B[(size_t)V_DIM * H_DIM];     // 128 MB
__device__ float g_sA[N_TOK];
__device__ float g_sB[V_DIM];
__device__ float g_pmax[(size_t)NVB * N_TOK];
__device__ float g_psum[(size_t)NVB * N_TOK];
__device__ float g_tlog[N_TOK];
__device__ int   g_tgt[N_TOK];
__device__ int   g_is64;

// ---------------- helpers ----------------
__device__ __forceinline__ uint32_t smem_u32(const void* p) {
    return (uint32_t)__cvta_generic_to_shared(p);
}
#define CP_ASYNC16(dst, src) \
    asm volatile("cp.async.cg.shared.global [%0], [%1], 16;" :: "r"(dst), "l"(src))
#define CP_COMMIT() asm volatile("cp.async.commit_group;" ::: "memory")
#define CP_WAIT1()  asm volatile("cp.async.wait_group 1;" ::: "memory")

__device__ __forceinline__ void ldm_x4(uint32_t& r0, uint32_t& r1, uint32_t& r2,
                                       uint32_t& r3, uint32_t addr) {
    asm volatile("ldmatrix.sync.aligned.m8n8.x4.shared.b16 {%0,%1,%2,%3}, [%4];"
                 : "=r"(r0), "=r"(r1), "=r"(r2), "=r"(r3) : "r"(addr));
}
// int8 IMMA: m16n8k32, s32 accumulate. 4096 MACs/instr.
__device__ __forceinline__ void mma16832(int* c, const uint32_t* a, const uint32_t* b) {
    asm volatile(
        "mma.sync.aligned.m16n8k32.row.col.s32.s8.s8.s32 "
        "{%0,%1,%2,%3}, {%4,%5,%6,%7}, {%8,%9}, {%0,%1,%2,%3};"
        : "+r"(c[0]), "+r"(c[1]), "+r"(c[2]), "+r"(c[3])
        : "r"(a[0]), "r"(a[1]), "r"(a[2]), "r"(a[3]), "r"(b[0]), "r"(b[1]));
}

// ---------------- target dtype sniffing + normalization ----------------
__global__ void detect_kernel(const int* __restrict__ t32) {
    __shared__ int flag;
    if (threadIdx.x == 0) flag = 0;
    __syncthreads();
    int local = 0;
    for (int i = threadIdx.x; i < N_TOK / 2; i += blockDim.x)
        local |= t32[2 * i + 1];
    if (local) atomicOr(&flag, 1);
    __syncthreads();
    if (threadIdx.x == 0) g_is64 = (flag == 0) ? 1 : 0;
}
__global__ void normalize_tgt_kernel(const int* __restrict__ t32) {
    const int i = blockIdx.x * blockDim.x + threadIdx.x;
    g_tgt[i] = g_is64 ? t32[2 * i] : t32[i];
}

// ---------------- fp32 -> int8 row-absmax quantization ----------------
// One block (128 threads) per row of 4096 floats; single global read, register-resident.
template <int NROWS>
__device__ __forceinline__ void quant_row(const float4* __restrict__ src,
                                          signed char* __restrict__ dst,
                                          float* __restrict__ srow) {
    const int row = blockIdx.x;
    const int tid = threadIdx.x;
    float4 v[8];
    float amax = 0.0f;
#pragma unroll
    for (int i = 0; i < 8; i++) {
        v[i] = src[(size_t)row * 1024 + tid + 128 * i];
        amax = fmaxf(amax, fmaxf(fmaxf(fabsf(v[i].x), fabsf(v[i].y)),
                                 fmaxf(fabsf(v[i].z), fabsf(v[i].w))));
    }
#pragma unroll
    for (int o = 16; o; o >>= 1) amax = fmaxf(amax, __shfl_xor_sync(0xffffffffu, amax, o));
    __shared__ float wmax[4];
    if ((tid & 31) == 0) wmax[tid >> 5] = amax;
    __syncthreads();
    amax = fmaxf(fmaxf(wmax[0], wmax[1]), fmaxf(wmax[2], wmax[3]));
    amax = fmaxf(amax, 1e-30f);
    if (tid == 0) srow[row] = amax * (1.0f / 127.0f);
    const float inv = 127.0f / amax;
#pragma unroll
    for (int i = 0; i < 8; i++) {
        char4 q;
        q.x = (signed char)__float2int_rn(v[i].x * inv);
        q.y = (signed char)__float2int_rn(v[i].y * inv);
        q.z = (signed char)__float2int_rn(v[i].z * inv);
        q.w = (signed char)__float2int_rn(v[i].w * inv);
        ((char4*)dst)[(size_t)row * 1024 + tid + 128 * i] = q;
    }
}
__global__ void quantA_kernel(const float4* __restrict__ src) { quant_row<N_TOK>(src, g_A, g_sA); }
__global__ void quantB_kernel(const float4* __restrict__ src) { quant_row<V_DIM>(src, g_B, g_sB); }

// ---------------- fused int8 GEMM + partial CE ----------------
// grid = (NRB, NVB), blockIdx.x fastest so a wave shares each weight tile via L2.
// 256 threads = 8 warps in a 2 (m) x 4 (n) grid, warp tile 64x64.
__global__ void __launch_bounds__(256, 1)
ce_gemm_kernel() {
    extern __shared__ char smem[];
    const int tid = threadIdx.x;
    const int wid = tid >> 5;
    const int l   = tid & 31;
    const int rb  = blockIdx.x;
    const int vb  = blockIdx.y;
    const int wm  = wid >> 2;     // 0..1
    const int wn  = wid & 3;      // 0..3
    const uint32_t sbase = smem_u32(smem);

    const signed char* Ag = g_A + (size_t)rb * BM * H_DIM;
    const signed char* Bg = g_B + (size_t)vb * BN * H_DIM;

    // cp.async: 1536 16B chunks per stage (A: 512, B: 1024), 6/thread.
    // smem row = 64B (4 chunks) = 64 int8, swizzle: phys_chunk = c ^ ((row>>1)&3)
    const char* gsrc[6];
    uint32_t    sdst[6];
#pragma unroll
    for (int i = 0; i < 6; i++) {
        int q = tid + 256 * i;
        if (q < 512) {
            int r = q >> 2, c = q & 3;
            gsrc[i] = (const char*)(Ag + (size_t)r * H_DIM + c * 16);
            sdst[i] = (uint32_t)(r * 64 + ((c ^ ((r >> 1) & 3)) << 4));
        } else {
            int b = q - 512, r = b >> 2, c = b & 3;
            gsrc[i] = (const char*)(Bg + (size_t)r * H_DIM + c * 16);
            sdst[i] = (uint32_t)(8192 + r * 64 + ((c ^ ((r >> 1) & 3)) << 4));
        }
    }

    // ldmatrix lane-constant addressing (identical geometry to fp16 version;
    // b16 ldmatrix fragments == s8 m16n8k32 fragments over 64-byte rows)
    const int rA = wm * 64 + (l & 15);
    const int cA = l >> 4;
    const int sA = (rA >> 1) & 3;
    const int nB = wn * 64 + ((l >> 4) << 3) + (l & 7);
    const int cB = (l >> 3) & 1;
    const int sB = (nB >> 1) & 3;

    int acc[4][8][4];
#pragma unroll
    for (int mt = 0; mt < 4; mt++)
#pragma unroll
        for (int nt = 0; nt < 8; nt++)
#pragma unroll
            for (int j = 0; j < 4; j++) acc[mt][nt][j] = 0;

    // prologue: stages 0, 1
#pragma unroll
    for (int st = 0; st < 2; st++) {
        uint32_t b = sbase + st * STAGE_BYTES;
#pragma unroll
        for (int i = 0; i < 6; i++) CP_ASYNC16(b + sdst[i], gsrc[i] + (size_t)st * BK);
        CP_COMMIT();
    }

    for (int k = 0; k < KITERS; k++) {
        CP_WAIT1();
        __syncthreads();
        if (k + 2 < KITERS) {
            uint32_t b = sbase + ((k + 2) % NSTAGE) * STAGE_BYTES;
#pragma unroll
            for (int i = 0; i < 6; i++)
                CP_ASYNC16(b + sdst[i], gsrc[i] + (size_t)(k + 2) * BK);
        }
        CP_COMMIT();   // unconditional: keeps wait_group<1> semantics exact

        const uint32_t ab = sbase + (k % NSTAGE) * STAGE_BYTES;
#pragma unroll
        for (int ks = 0; ks < 2; ks++) {    // 2 x k32 per 64-byte block
            uint32_t a[4][4], b[4][4];
#pragma unroll
            for (int mt = 0; mt < 4; mt++)
                ldm_x4(a[mt][0], a[mt][1], a[mt][2], a[mt][3],
                       ab + (uint32_t)((rA + mt * 16) * 64 + (((ks * 2 + cA) ^ sA) << 4)));
#pragma unroll
            for (int p = 0; p < 4; p++)
                ldm_x4(b[p][0], b[p][1], b[p][2], b[p][3],
                       ab + 8192 + (uint32_t)((nB + p * 16) * 64 + (((ks * 2 + cB) ^ sB) << 4)));
#pragma unroll
            for (int mt = 0; mt < 4; mt++)
#pragma unroll
                for (int p = 0; p < 4; p++) {
                    mma16832(acc[mt][2 * p],     a[mt], &b[p][0]);
                    mma16832(acc[mt][2 * p + 1], a[mt], &b[p][2]);
                }
        }
    }

    // ---------------- epilogue: dequant + row max/sumexp/target ----------------
    __syncthreads();   // all tile reads done; smem reused
    float* sm_m = (float*)smem;          // [4][128]
    float* sm_s = sm_m + 512;
    float* sm_t = sm_s + 512;
    float* sm_b = sm_t + 512;            // [256] col scales
    float* sm_a = sm_b + 256;            // [128] row scales
    if (tid < 256) sm_b[tid] = g_sB[vb * BN + tid];
    if (tid < 128) sm_a[tid] = g_sA[rb * BM + tid];
    __syncthreads();
    const int* tgt_base = g_tgt + rb * BM;

#pragma unroll
    for (int mt = 0; mt < 4; mt++) {
#pragma unroll
        for (int slot = 0; slot < 2; slot++) {
            const int rloc = wm * 64 + mt * 16 + (l >> 2) + slot * 8;
            const float sAr = sm_a[rloc];
            const int colb = wn * 64 + (l & 3) * 2;
            float x[8][2];
            float m = -1e30f;
#pragma unroll
            for (int nt = 0; nt < 8; nt++) {
                x[nt][0] = (float)acc[mt][nt][2 * slot]     * sAr * sm_b[colb + nt * 8];
                x[nt][1] = (float)acc[mt][nt][2 * slot + 1] * sAr * sm_b[colb + nt * 8 + 1];
                m = fmaxf(m, fmaxf(x[nt][0], x[nt][1]));
            }
            m = fmaxf(m, __shfl_xor_sync(0xffffffffu, m, 1));
            m = fmaxf(m, __shfl_xor_sync(0xffffffffu, m, 2));
            const int tl = tgt_base[rloc] - vb * BN;
            float s = 0.0f, tv = 0.0f;
#pragma unroll
            for (int nt = 0; nt < 8; nt++) {
                s += __expf(x[nt][0] - m) + __expf(x[nt][1] - m);
                int c0 = colb + nt * 8;
                if (c0 == tl)     tv = x[nt][0];
                if (c0 + 1 == tl) tv = x[nt][1];
            }
            s  += __shfl_xor_sync(0xffffffffu, s, 1);
            s  += __shfl_xor_sync(0xffffffffu, s, 2);
            tv += __shfl_xor_sync(0xffffffffu, tv, 1);
            tv += __shfl_xor_sync(0xffffffffu, tv, 2);
            if ((l & 3) == 0) {
                sm_m[wn * 128 + rloc] = m;
                sm_s[wn * 128 + rloc] = s;
                sm_t[wn * 128 + rloc] = tv;
            }
        }
    }
    __syncthreads();
    if (tid < BM) {
        const int rg = rb * BM + tid;
        float m = sm_m[tid];
#pragma unroll
        for (int w = 1; w < 4; w++) m = fmaxf(m, sm_m[w * 128 + tid]);
        float s = 0.0f, tv = 0.0f;
#pragma unroll
        for (int w = 0; w < 4; w++) {
            s  += sm_s[w * 128 + tid] * __expf(sm_m[w * 128 + tid] - m);
            tv += sm_t[w * 128 + tid];
        }
        g_pmax[(size_t)vb * N_TOK + rg] = m;
        g_psum[(size_t)vb * N_TOK + rg] = s;
        int t = g_tgt[rg];
        int lo = vb * BN;
        if (t >= lo && t < lo + BN) g_tlog[rg] = tv;
    }
}

// ---------------- final logsumexp merge + mean ----------------
__global__ void reduce_kernel(float* __restrict__ out) {
    const int row = blockIdx.x * blockDim.x + threadIdx.x;
    float m = -1e30f;
    for (int i = 0; i < NVB; i++) m = fmaxf(m, g_pmax[(size_t)i * N_TOK + row]);
    float s = 0.0f;
    for (int i = 0; i < NVB; i++)
        s += g_psum[(size_t)i * N_TOK + row] * __expf(g_pmax[(size_t)i * N_TOK + row] - m);
    float nll = m + logf(s) - g_tlog[row];
#pragma unroll
    for (int o = 16; o; o >>= 1) nll += __shfl_xor_sync(0xffffffffu, nll, o);
    __shared__ float ws[8];
    if ((threadIdx.x & 31) == 0) ws[threadIdx.x >> 5] = nll;
    __syncthreads();
    if (threadIdx.x < 8) {
        float v = ws[threadIdx.x];
#pragma unroll
        for (int o = 4; o; o >>= 1) v += __shfl_xor_sync(0xffu, v, o);
        if (threadIdx.x == 0) atomicAdd(out, v / (float)N_TOK);
    }
}

// ---------------- launch ----------------
extern "C" void kernel_launch(void* const* d_in, const int* in_sizes, int n_in,
                              void* d_out, int out_size) {
    const float* input = (const float*)d_in[0];
    const float* weight = (const float*)d_in[1];
    const int* target32 = (const int*)d_in[2];
    float* out = (float*)d_out;

    cudaFuncSetAttribute(ce_gemm_kernel, cudaFuncAttributeMaxDynamicSharedMemorySize,
                         SMEM_TOTAL);

    detect_kernel<<<1, 1024>>>(target32);
    normalize_tgt_kernel<<<N_TOK / 256, 256>>>(target32);
    quantA_kernel<<<N_TOK, 128>>>((const float4*)input);
    quantB_kernel<<<V_DIM, 128>>>((const float4*)weight);
    cudaMemsetAsync(d_out, 0, sizeof(float));
    ce_gemm_kernel<<<dim3(NRB, NVB), 256, SMEM_TOTAL>>>();
    reduce_kernel<<<N_TOK / 256, 256>>>(out);
}

// round 6
// speedup vs baseline: 2.5701x; 2.5701x over previous
#include <cuda_runtime.h>
#include <cuda_fp16.h>
#include <cstdint>

// Problem dims
#define N_TOK 8192
#define H_DIM 4096
#define V_DIM 32000
// Tiling
#define BM 128
#define BN 256
#define BK 32
#define KITERS (H_DIM / BK)   // 128
#define NVB (V_DIM / BN)      // 125
#define NRB (N_TOK / BM)      // 64
#define STAGE_BYTES 24576     // A 8KB + B 16KB
#define NSTAGE 3
#define SMEM_TOTAL (STAGE_BYTES * NSTAGE)   // 73728

// Scratch (static __device__ arrays: allocation-free per harness rules)
__device__ __half g_A[(size_t)N_TOK * H_DIM];     // 64 MB
__device__ __half g_B[(size_t)V_DIM * H_DIM];     // 256 MB
__device__ float g_pmax[(size_t)NVB * N_TOK];
__device__ float g_psum[(size_t)NVB * N_TOK];
__device__ float g_tlog[N_TOK];
__device__ int   g_tgt[N_TOK];
__device__ int   g_is64;

// ---------------- helpers ----------------
__device__ __forceinline__ uint32_t smem_u32(const void* p) {
    return (uint32_t)__cvta_generic_to_shared(p);
}
#define CP_ASYNC16(dst, src) \
    asm volatile("cp.async.cg.shared.global [%0], [%1], 16;" :: "r"(dst), "l"(src))
#define CP_COMMIT() asm volatile("cp.async.commit_group;" ::: "memory")
#define CP_WAIT1()  asm volatile("cp.async.wait_group 1;" ::: "memory")

__device__ __forceinline__ void ldm_x4(uint32_t& r0, uint32_t& r1, uint32_t& r2,
                                       uint32_t& r3, uint32_t addr) {
    asm volatile("ldmatrix.sync.aligned.m8n8.x4.shared.b16 {%0,%1,%2,%3}, [%4];"
                 : "=r"(r0), "=r"(r1), "=r"(r2), "=r"(r3) : "r"(addr));
}
// fp16 MMA with **fp16 accumulate** (full-rate legacy HMMA form; 2 acc regs)
__device__ __forceinline__ void mma16816h(uint32_t* c, const uint32_t* a, const uint32_t* b) {
    asm volatile(
        "mma.sync.aligned.m16n8k16.row.col.f16.f16.f16.f16 "
        "{%0,%1}, {%2,%3,%4,%5}, {%6,%7}, {%0,%1};"
        : "+r"(c[0]), "+r"(c[1])
        : "r"(a[0]), "r"(a[1]), "r"(a[2]), "r"(a[3]), "r"(b[0]), "r"(b[1]));
}

// ---------------- target dtype sniffing + normalization ----------------
__global__ void detect_kernel(const int* __restrict__ t32) {
    __shared__ int flag;
    if (threadIdx.x == 0) flag = 0;
    __syncthreads();
    int local = 0;
    for (int i = threadIdx.x; i < N_TOK / 2; i += blockDim.x)
        local |= t32[2 * i + 1];
    if (local) atomicOr(&flag, 1);
    __syncthreads();
    if (threadIdx.x == 0) g_is64 = (flag == 0) ? 1 : 0;
}
__global__ void normalize_tgt_kernel(const int* __restrict__ t32) {
    const int i = blockIdx.x * blockDim.x + threadIdx.x;
    g_tgt[i] = g_is64 ? t32[2 * i] : t32[i];
}

// ---------------- fp32 -> fp16 conversion ----------------
__global__ void cvtA_kernel(const float4* __restrict__ src) {
    const int n4 = N_TOK * H_DIM / 4;
    __half2* d = (__half2*)g_A;
    for (int i = blockIdx.x * blockDim.x + threadIdx.x; i < n4;
         i += gridDim.x * blockDim.x) {
        float4 v = src[i];
        d[2 * i]     = __floats2half2_rn(v.x, v.y);
        d[2 * i + 1] = __floats2half2_rn(v.z, v.w);
    }
}
__global__ void cvtB_kernel(const float4* __restrict__ src) {
    const int n4 = V_DIM * H_DIM / 4;
    __half2* d = (__half2*)g_B;
    for (int i = blockIdx.x * blockDim.x + threadIdx.x; i < n4;
         i += gridDim.x * blockDim.x) {
        float4 v = src[i];
        d[2 * i]     = __floats2half2_rn(v.x, v.y);
        d[2 * i + 1] = __floats2half2_rn(v.z, v.w);
    }
}

// ---------------- fused GEMM + partial CE ----------------
// grid = (NRB, NVB), blockIdx.x fastest so a wave shares each weight tile via L2.
// 256 threads = 8 warps in a 2 (m) x 4 (n) grid, warp tile 64x64.
__global__ void __launch_bounds__(256, 1)
ce_gemm_kernel() {
    extern __shared__ char smem[];
    const int tid = threadIdx.x;
    const int wid = tid >> 5;
    const int l   = tid & 31;
    const int rb  = blockIdx.x;
    const int vb  = blockIdx.y;
    const int wm  = wid >> 2;     // 0..1
    const int wn  = wid & 3;      // 0..3
    const uint32_t sbase = smem_u32(smem);

    const __half* Ag = g_A + (size_t)rb * BM * H_DIM;
    const __half* Bg = g_B + (size_t)vb * BN * H_DIM;

    // cp.async: 1536 16B chunks per stage (A: 512, B: 1024), 6/thread.
    // smem row = 64B (4 chunks), swizzle: phys_chunk = c ^ ((row>>1)&3)
    const char* gsrc[6];
    uint32_t    sdst[6];
#pragma unroll
    for (int i = 0; i < 6; i++) {
        int q = tid + 256 * i;
        if (q < 512) {
            int r = q >> 2, c = q & 3;
            gsrc[i] = (const char*)(Ag + (size_t)r * H_DIM + c * 8);
            sdst[i] = (uint32_t)(r * 64 + ((c ^ ((r >> 1) & 3)) << 4));
        } else {
            int b = q - 512, r = b >> 2, c = b & 3;
            gsrc[i] = (const char*)(Bg + (size_t)r * H_DIM + c * 8);
            sdst[i] = (uint32_t)(8192 + r * 64 + ((c ^ ((r >> 1) & 3)) << 4));
        }
    }

    // ldmatrix lane-constant addressing
    const int rA = wm * 64 + (l & 15);
    const int cA = l >> 4;
    const int sA = (rA >> 1) & 3;
    const int nB = wn * 64 + ((l >> 4) << 3) + (l & 7);
    const int cB = (l >> 3) & 1;
    const int sB = (nB >> 1) & 3;

    // f16 accumulators: [mt][nt][slot], slot0 = rows r..r (cols c,c+1), slot1 = row r+8
    uint32_t acc[4][8][2];
#pragma unroll
    for (int mt = 0; mt < 4; mt++)
#pragma unroll
        for (int nt = 0; nt < 8; nt++) {
            acc[mt][nt][0] = 0u;
            acc[mt][nt][1] = 0u;
        }

    // prologue: stages 0, 1
#pragma unroll
    for (int st = 0; st < 2; st++) {
        uint32_t b = sbase + st * STAGE_BYTES;
#pragma unroll
        for (int i = 0; i < 6; i++) CP_ASYNC16(b + sdst[i], gsrc[i] + (size_t)st * (BK * 2));
        CP_COMMIT();
    }

    for (int k = 0; k < KITERS; k++) {
        CP_WAIT1();
        __syncthreads();
        if (k + 2 < KITERS) {
            uint32_t b = sbase + ((k + 2) % NSTAGE) * STAGE_BYTES;
#pragma unroll
            for (int i = 0; i < 6; i++)
                CP_ASYNC16(b + sdst[i], gsrc[i] + (size_t)(k + 2) * (BK * 2));
        }
        CP_COMMIT();   // unconditional: keeps wait_group<1> semantics exact

        const uint32_t ab = sbase + (k % NSTAGE) * STAGE_BYTES;
#pragma unroll
        for (int ks = 0; ks < 2; ks++) {
            uint32_t a[4][4], b[4][4];
#pragma unroll
            for (int mt = 0; mt < 4; mt++)
                ldm_x4(a[mt][0], a[mt][1], a[mt][2], a[mt][3],
                       ab + (uint32_t)((rA + mt * 16) * 64 + (((ks * 2 + cA) ^ sA) << 4)));
#pragma unroll
            for (int p = 0; p < 4; p++)
                ldm_x4(b[p][0], b[p][1], b[p][2], b[p][3],
                       ab + 8192 + (uint32_t)((nB + p * 16) * 64 + (((ks * 2 + cB) ^ sB) << 4)));
#pragma unroll
            for (int mt = 0; mt < 4; mt++)
#pragma unroll
                for (int p = 0; p < 4; p++) {
                    mma16816h(acc[mt][2 * p],     a[mt], &b[p][0]);
                    mma16816h(acc[mt][2 * p + 1], a[mt], &b[p][2]);
                }
        }
    }

    // ---------------- epilogue ----------------
    __syncthreads();   // all tile reads done; smem reused for partials
    float* sm_m = (float*)smem;          // [4][128]
    float* sm_s = sm_m + 512;
    float* sm_t = sm_s + 512;
    const int* tgt_base = g_tgt + rb * BM;

#pragma unroll
    for (int mt = 0; mt < 4; mt++) {
#pragma unroll
        for (int slot = 0; slot < 2; slot++) {
            const int rloc = wm * 64 + mt * 16 + (l >> 2) + slot * 8;
            float x[8][2];
            float m = -1e30f;
#pragma unroll
            for (int nt = 0; nt < 8; nt++) {
                float2 f = __half22float2(*(__half2*)&acc[mt][nt][slot]);
                x[nt][0] = f.x;
                x[nt][1] = f.y;
                m = fmaxf(m, fmaxf(f.x, f.y));
            }
            m = fmaxf(m, __shfl_xor_sync(0xffffffffu, m, 1));
            m = fmaxf(m, __shfl_xor_sync(0xffffffffu, m, 2));
            const int tl = tgt_base[rloc] - vb * BN;
            float s = 0.0f, tv = 0.0f;
            const int colb = wn * 64 + (l & 3) * 2;
#pragma unroll
            for (int nt = 0; nt < 8; nt++) {
                s += __expf(x[nt][0] - m) + __expf(x[nt][1] - m);
                int c0 = colb + nt * 8;
                if (c0 == tl)     tv = x[nt][0];
                if (c0 + 1 == tl) tv = x[nt][1];
            }
            s  += __shfl_xor_sync(0xffffffffu, s, 1);
            s  += __shfl_xor_sync(0xffffffffu, s, 2);
            tv += __shfl_xor_sync(0xffffffffu, tv, 1);
            tv += __shfl_xor_sync(0xffffffffu, tv, 2);
            if ((l & 3) == 0) {
                sm_m[wn * 128 + rloc] = m;
                sm_s[wn * 128 + rloc] = s;
                sm_t[wn * 128 + rloc] = tv;
            }
        }
    }
    __syncthreads();
    if (tid < BM) {
        const int rg = rb * BM + tid;
        float m = sm_m[tid];
#pragma unroll
        for (int w = 1; w < 4; w++) m = fmaxf(m, sm_m[w * 128 + tid]);
        float s = 0.0f, tv = 0.0f;
#pragma unroll
        for (int w = 0; w < 4; w++) {
            s  += sm_s[w * 128 + tid] * __expf(sm_m[w * 128 + tid] - m);
            tv += sm_t[w * 128 + tid];
        }
        g_pmax[(size_t)vb * N_TOK + rg] = m;
        g_psum[(size_t)vb * N_TOK + rg] = s;
        int t = g_tgt[rg];
        int lo = vb * BN;
        if (t >= lo && t < lo + BN) g_tlog[rg] = tv;
    }
}

// ---------------- final logsumexp merge + mean ----------------
__global__ void reduce_kernel(float* __restrict__ out) {
    const int row = blockIdx.x * blockDim.x + threadIdx.x;
    float m = -1e30f;
    for (int i = 0; i < NVB; i++) m = fmaxf(m, g_pmax[(size_t)i * N_TOK + row]);
    float s = 0.0f;
    for (int i = 0; i < NVB; i++)
        s += g_psum[(size_t)i * N_TOK + row] * __expf(g_pmax[(size_t)i * N_TOK + row] - m);
    float nll = m + logf(s) - g_tlog[row];
#pragma unroll
    for (int o = 16; o; o >>= 1) nll += __shfl_xor_sync(0xffffffffu, nll, o);
    __shared__ float ws[8];
    if ((threadIdx.x & 31) == 0) ws[threadIdx.x >> 5] = nll;
    __syncthreads();
    if (threadIdx.x < 8) {
        float v = ws[threadIdx.x];
#pragma unroll
        for (int o = 4; o; o >>= 1) v += __shfl_xor_sync(0xffu, v, o);
        if (threadIdx.x == 0) atomicAdd(out, v / (float)N_TOK);
    }
}

// ---------------- launch ----------------
extern "C" void kernel_launch(void* const* d_in, const int* in_sizes, int n_in,
                              void* d_out, int out_size) {
    const float* input = (const float*)d_in[0];
    const float* weight = (const float*)d_in[1];
    const int* target32 = (const int*)d_in[2];
    float* out = (float*)d_out;

    cudaFuncSetAttribute(ce_gemm_kernel, cudaFuncAttributeMaxDynamicSharedMemorySize,
                         SMEM_TOTAL);

    detect_kernel<<<1, 1024>>>(target32);
    normalize_tgt_kernel<<<N_TOK / 256, 256>>>(target32);
    cvtA_kernel<<<4096, 256>>>((const float4*)input);
    cvtB_kernel<<<8192, 256>>>((const float4*)weight);
    cudaMemsetAsync(d_out, 0, sizeof(float));
    ce_gemm_kernel<<<dim3(NRB, NVB), 256, SMEM_TOTAL>>>();
    reduce_kernel<<<N_TOK / 256, 256>>>(out);
}

// round 7
// speedup vs baseline: 3.1237x; 1.2154x over previous
#include <cuda_runtime.h>
#include <cuda_fp16.h>
#include <cstdint>

// Problem dims
#define N_TOK 8192
#define H_DIM 4096
#define V_DIM 32000
// Tiling
#define BM 128
#define BN 256
#define BK 32
#define KITERS (H_DIM / BK)   // 128
#define NVB (V_DIM / BN)      // 125
#define NRB (N_TOK / BM)      // 64
#define STAGE_BYTES 24576     // A 8KB + B 16KB
#define NSTAGE 3
#define SMEM_TOTAL (STAGE_BYTES * NSTAGE)   // 73728

// Scratch (static __device__ arrays: allocation-free per harness rules)
__device__ __half g_A[(size_t)N_TOK * H_DIM];     // 64 MB
__device__ __half g_B[(size_t)V_DIM * H_DIM];     // 256 MB
__device__ float g_pmax[(size_t)NVB * N_TOK];
__device__ float g_psum[(size_t)NVB * N_TOK];
__device__ float g_tlog[N_TOK];
__device__ int   g_tgt[N_TOK];
__device__ int   g_is64;

// ---------------- helpers ----------------
__device__ __forceinline__ uint32_t smem_u32(const void* p) {
    return (uint32_t)__cvta_generic_to_shared(p);
}
#define CP_ASYNC16(dst, src) \
    asm volatile("cp.async.cg.shared.global [%0], [%1], 16;" :: "r"(dst), "l"(src))
#define CP_COMMIT() asm volatile("cp.async.commit_group;" ::: "memory")
#define CP_WAIT1()  asm volatile("cp.async.wait_group 1;" ::: "memory")

__device__ __forceinline__ void ldm_x4(uint32_t& r0, uint32_t& r1, uint32_t& r2,
                                       uint32_t& r3, uint32_t addr) {
    asm volatile("ldmatrix.sync.aligned.m8n8.x4.shared.b16 {%0,%1,%2,%3}, [%4];"
                 : "=r"(r0), "=r"(r1), "=r"(r2), "=r"(r3) : "r"(addr));
}
// fp16 MMA with fp16 accumulate (2 acc regs -> enables occupancy 2)
__device__ __forceinline__ void mma16816h(uint32_t* c, const uint32_t* a, const uint32_t* b) {
    asm volatile(
        "mma.sync.aligned.m16n8k16.row.col.f16.f16.f16.f16 "
        "{%0,%1}, {%2,%3,%4,%5}, {%6,%7}, {%0,%1};"
        : "+r"(c[0]), "+r"(c[1])
        : "r"(a[0]), "r"(a[1]), "r"(a[2]), "r"(a[3]), "r"(b[0]), "r"(b[1]));
}

// ---------------- target dtype sniffing + normalization ----------------
__global__ void detect_kernel(const int* __restrict__ t32) {
    __shared__ int flag;
    if (threadIdx.x == 0) flag = 0;
    __syncthreads();
    int local = 0;
    for (int i = threadIdx.x; i < N_TOK / 2; i += blockDim.x)
        local |= t32[2 * i + 1];
    if (local) atomicOr(&flag, 1);
    __syncthreads();
    if (threadIdx.x == 0) g_is64 = (flag == 0) ? 1 : 0;
}
__global__ void normalize_tgt_kernel(const int* __restrict__ t32) {
    const int i = blockIdx.x * blockDim.x + threadIdx.x;
    g_tgt[i] = g_is64 ? t32[2 * i] : t32[i];
}

// ---------------- fp32 -> fp16 conversion ----------------
__global__ void cvtA_kernel(const float4* __restrict__ src) {
    const int n4 = N_TOK * H_DIM / 4;
    __half2* d = (__half2*)g_A;
    for (int i = blockIdx.x * blockDim.x + threadIdx.x; i < n4;
         i += gridDim.x * blockDim.x) {
        float4 v = src[i];
        d[2 * i]     = __floats2half2_rn(v.x, v.y);
        d[2 * i + 1] = __floats2half2_rn(v.z, v.w);
    }
}
__global__ void cvtB_kernel(const float4* __restrict__ src) {
    const int n4 = V_DIM * H_DIM / 4;
    __half2* d = (__half2*)g_B;
    for (int i = blockIdx.x * blockDim.x + threadIdx.x; i < n4;
         i += gridDim.x * blockDim.x) {
        float4 v = src[i];
        d[2 * i]     = __floats2half2_rn(v.x, v.y);
        d[2 * i + 1] = __floats2half2_rn(v.z, v.w);
    }
}

// ---------------- fused GEMM + partial CE ----------------
// grid = (NRB, NVB), blockIdx.x fastest so a wave shares each weight tile via L2.
// 256 threads = 8 warps in a 2 (m) x 4 (n) grid, warp tile 64x64. occupancy 2.
__global__ void __launch_bounds__(256, 2)
ce_gemm_kernel() {
    extern __shared__ char smem[];
    const int tid = threadIdx.x;
    const int wid = tid >> 5;
    const int l   = tid & 31;
    const int rb  = blockIdx.x;
    const int vb  = blockIdx.y;
    const int wm  = wid >> 2;     // 0..1
    const int wn  = wid & 3;      // 0..3
    const uint32_t sbase = smem_u32(smem);

    const __half* Ag = g_A + (size_t)rb * BM * H_DIM;
    const __half* Bg = g_B + (size_t)vb * BN * H_DIM;

    // cp.async: 1536 16B chunks per stage (A: 512, B: 1024), 6/thread.
    // smem row = 64B (4 chunks), swizzle: phys_chunk = c ^ ((row>>1)&3)
    const char* gsrc[6];
    uint32_t    sdst[6];
#pragma unroll
    for (int i = 0; i < 6; i++) {
        int q = tid + 256 * i;
        if (q < 512) {
            int r = q >> 2, c = q & 3;
            gsrc[i] = (const char*)(Ag + (size_t)r * H_DIM + c * 8);
            sdst[i] = (uint32_t)(r * 64 + ((c ^ ((r >> 1) & 3)) << 4));
        } else {
            int b = q - 512, r = b >> 2, c = b & 3;
            gsrc[i] = (const char*)(Bg + (size_t)r * H_DIM + c * 8);
            sdst[i] = (uint32_t)(8192 + r * 64 + ((c ^ ((r >> 1) & 3)) << 4));
        }
    }

    // ldmatrix lane-constant addressing
    const int rA = wm * 64 + (l & 15);
    const int cA = l >> 4;
    const int sA = (rA >> 1) & 3;
    const int nB = wn * 64 + ((l >> 4) << 3) + (l & 7);
    const int cB = (l >> 3) & 1;
    const int sB = (nB >> 1) & 3;

    // f16 accumulators: [mt][nt][slot]
    uint32_t acc[4][8][2];
#pragma unroll
    for (int mt = 0; mt < 4; mt++)
#pragma unroll
        for (int nt = 0; nt < 8; nt++) {
            acc[mt][nt][0] = 0u;
            acc[mt][nt][1] = 0u;
        }

    // prologue: stages 0, 1
#pragma unroll
    for (int st = 0; st < 2; st++) {
        uint32_t b = sbase + st * STAGE_BYTES;
#pragma unroll
        for (int i = 0; i < 6; i++) CP_ASYNC16(b + sdst[i], gsrc[i] + (size_t)st * (BK * 2));
        CP_COMMIT();
    }

    for (int k = 0; k < KITERS; k++) {
        CP_WAIT1();
        __syncthreads();
        if (k + 2 < KITERS) {
            uint32_t b = sbase + ((k + 2) % NSTAGE) * STAGE_BYTES;
#pragma unroll
            for (int i = 0; i < 6; i++)
                CP_ASYNC16(b + sdst[i], gsrc[i] + (size_t)(k + 2) * (BK * 2));
        }
        CP_COMMIT();   // unconditional: keeps wait_group<1> semantics exact

        const uint32_t ab = sbase + (k % NSTAGE) * STAGE_BYTES;
#pragma unroll
        for (int ks = 0; ks < 2; ks++) {
            uint32_t a[4][4], b[4][4];
#pragma unroll
            for (int mt = 0; mt < 4; mt++)
                ldm_x4(a[mt][0], a[mt][1], a[mt][2], a[mt][3],
                       ab + (uint32_t)((rA + mt * 16) * 64 + (((ks * 2 + cA) ^ sA) << 4)));
#pragma unroll
            for (int p = 0; p < 4; p++)
                ldm_x4(b[p][0], b[p][1], b[p][2], b[p][3],
                       ab + 8192 + (uint32_t)((nB + p * 16) * 64 + (((ks * 2 + cB) ^ sB) << 4)));
#pragma unroll
            for (int mt = 0; mt < 4; mt++)
#pragma unroll
                for (int p = 0; p < 4; p++) {
                    mma16816h(acc[mt][2 * p],     a[mt], &b[p][0]);
                    mma16816h(acc[mt][2 * p + 1], a[mt], &b[p][2]);
                }
        }
    }

    // ---------------- epilogue ----------------
    __syncthreads();   // all tile reads done; smem reused for partials
    float* sm_m = (float*)smem;          // [4][128]
    float* sm_s = sm_m + 512;
    float* sm_t = sm_s + 512;
    const int* tgt_base = g_tgt + rb * BM;

#pragma unroll
    for (int mt = 0; mt < 4; mt++) {
#pragma unroll
        for (int slot = 0; slot < 2; slot++) {
            const int rloc = wm * 64 + mt * 16 + (l >> 2) + slot * 8;
            float x[8][2];
            float m = -1e30f;
#pragma unroll
            for (int nt = 0; nt < 8; nt++) {
                float2 f = __half22float2(*(__half2*)&acc[mt][nt][slot]);
                x[nt][0] = f.x;
                x[nt][1] = f.y;
                m = fmaxf(m, fmaxf(f.x, f.y));
            }
            m = fmaxf(m, __shfl_xor_sync(0xffffffffu, m, 1));
            m = fmaxf(m, __shfl_xor_sync(0xffffffffu, m, 2));
            const int tl = tgt_base[rloc] - vb * BN;
            float s = 0.0f, tv = 0.0f;
            const int colb = wn * 64 + (l & 3) * 2;
#pragma unroll
            for (int nt = 0; nt < 8; nt++) {
                s += __expf(x[nt][0] - m) + __expf(x[nt][1] - m);
                int c0 = colb + nt * 8;
                if (c0 == tl)     tv = x[nt][0];
                if (c0 + 1 == tl) tv = x[nt][1];
            }
            s  += __shfl_xor_sync(0xffffffffu, s, 1);
            s  += __shfl_xor_sync(0xffffffffu, s, 2);
            tv += __shfl_xor_sync(0xffffffffu, tv, 1);
            tv += __shfl_xor_sync(0xffffffffu, tv, 2);
            if ((l & 3) == 0) {
                sm_m[wn * 128 + rloc] = m;
                sm_s[wn * 128 + rloc] = s;
                sm_t[wn * 128 + rloc] = tv;
            }
        }
    }
    __syncthreads();
    if (tid < BM) {
        const int rg = rb * BM + tid;
        float m = sm_m[tid];
#pragma unroll
        for (int w = 1; w < 4; w++) m = fmaxf(m, sm_m[w * 128 + tid]);
        float s = 0.0f, tv = 0.0f;
#pragma unroll
        for (int w = 0; w < 4; w++) {
            s  += sm_s[w * 128 + tid] * __expf(sm_m[w * 128 + tid] - m);
            tv += sm_t[w * 128 + tid];
        }
        g_pmax[(size_t)vb * N_TOK + rg] = m;
        g_psum[(size_t)vb * N_TOK + rg] = s;
        int t = g_tgt[rg];
        int lo = vb * BN;
        if (t >= lo && t < lo + BN) g_tlog[rg] = tv;
    }
}

// ---------------- final logsumexp merge + mean ----------------
__global__ void reduce_kernel(float* __restrict__ out) {
    const int row = blockIdx.x * blockDim.x + threadIdx.x;
    float m = -1e30f;
    for (int i = 0; i < NVB; i++) m = fmaxf(m, g_pmax[(size_t)i * N_TOK + row]);
    float s = 0.0f;
    for (int i = 0; i < NVB; i++)
        s += g_psum[(size_t)i * N_TOK + row] * __expf(g_pmax[(size_t)i * N_TOK + row] - m);
    float nll = m + logf(s) - g_tlog[row];
#pragma unroll
    for (int o = 16; o; o >>= 1) nll += __shfl_xor_sync(0xffffffffu, nll, o);
    __shared__ float ws[8];
    if ((threadIdx.x & 31) == 0) ws[threadIdx.x >> 5] = nll;
    __syncthreads();
    if (threadIdx.x < 8) {
        float v = ws[threadIdx.x];
#pragma unroll
        for (int o = 4; o; o >>= 1) v += __shfl_xor_sync(0xffu, v, o);
        if (threadIdx.x == 0) atomicAdd(out, v / (float)N_TOK);
    }
}

// ---------------- launch ----------------
extern "C" void kernel_launch(void* const* d_in, const int* in_sizes, int n_in,
                              void* d_out, int out_size) {
    const float* input = (const float*)d_in[0];
    const float* weight = (const float*)d_in[1];
    const int* target32 = (const int*)d_in[2];
    float* out = (float*)d_out;

    cudaFuncSetAttribute(ce_gemm_kernel, cudaFuncAttributeMaxDynamicSharedMemorySize,
                         SMEM_TOTAL);

    detect_kernel<<<1, 1024>>>(target32);
    normalize_tgt_kernel<<<N_TOK / 256, 256>>>(target32);
    cvtA_kernel<<<4096, 256>>>((const float4*)input);
    cvtB_kernel<<<8192, 256>>>((const float4*)weight);
    cudaMemsetAsync(d_out, 0, sizeof(float));
    ce_gemm_kernel<<<dim3(NRB, NVB), 256, SMEM_TOTAL>>>();
    reduce_kernel<<<N_TOK / 256, 256>>>(out);
}

// round 8
// speedup vs baseline: 3.1260x; 1.0007x over previous
#include <cuda_runtime.h>
#include <cuda_fp16.h>
#include <cstdint>

// Problem dims
#define N_TOK 8192
#define H_DIM 4096
#define V_DIM 32000
// Tiling
#define BM 128
#define BN 256
#define BK 32
#define KITERS (H_DIM / BK)   // 128
#define NVB (V_DIM / BN)      // 125
#define NRB (N_TOK / BM)      // 64
#define STAGE_BYTES 24576     // A 8KB + B 16KB
#define NSTAGE 4
#define SMEM_TOTAL (STAGE_BYTES * NSTAGE)   // 98304

// Scratch (static __device__ arrays: allocation-free per harness rules)
__device__ __half g_A[(size_t)N_TOK * H_DIM];     // 64 MB
__device__ __half g_B[(size_t)V_DIM * H_DIM];     // 256 MB
__device__ float g_pmax[(size_t)NVB * N_TOK];
__device__ float g_psum[(size_t)NVB * N_TOK];
__device__ float g_tlog[N_TOK];
__device__ int   g_tgt[N_TOK];
__device__ int   g_is64;

// ---------------- helpers ----------------
__device__ __forceinline__ uint32_t smem_u32(const void* p) {
    return (uint32_t)__cvta_generic_to_shared(p);
}
#define CP_ASYNC16(dst, src) \
    asm volatile("cp.async.cg.shared.global [%0], [%1], 16;" :: "r"(dst), "l"(src))
#define CP_COMMIT() asm volatile("cp.async.commit_group;" ::: "memory")
#define CP_WAIT2()  asm volatile("cp.async.wait_group 2;" ::: "memory")

__device__ __forceinline__ void ldm_x4(uint32_t& r0, uint32_t& r1, uint32_t& r2,
                                       uint32_t& r3, uint32_t addr) {
    asm volatile("ldmatrix.sync.aligned.m8n8.x4.shared.b16 {%0,%1,%2,%3}, [%4];"
                 : "=r"(r0), "=r"(r1), "=r"(r2), "=r"(r3) : "r"(addr));
}
// fp16 MMA with fp16 accumulate (2 acc regs -> enables occupancy 2)
__device__ __forceinline__ void mma16816h(uint32_t* c, const uint32_t* a, const uint32_t* b) {
    asm volatile(
        "mma.sync.aligned.m16n8k16.row.col.f16.f16.f16.f16 "
        "{%0,%1}, {%2,%3,%4,%5}, {%6,%7}, {%0,%1};"
        : "+r"(c[0]), "+r"(c[1])
        : "r"(a[0]), "r"(a[1]), "r"(a[2]), "r"(a[3]), "r"(b[0]), "r"(b[1]));
}

// ---------------- target dtype sniffing + normalization ----------------
__global__ void detect_kernel(const int* __restrict__ t32) {
    __shared__ int flag;
    if (threadIdx.x == 0) flag = 0;
    __syncthreads();
    int local = 0;
    for (int i = threadIdx.x; i < N_TOK / 2; i += blockDim.x)
        local |= t32[2 * i + 1];
    if (local) atomicOr(&flag, 1);
    __syncthreads();
    if (threadIdx.x == 0) g_is64 = (flag == 0) ? 1 : 0;
}
__global__ void normalize_tgt_kernel(const int* __restrict__ t32) {
    const int i = blockIdx.x * blockDim.x + threadIdx.x;
    g_tgt[i] = g_is64 ? t32[2 * i] : t32[i];
}

// ---------------- fp32 -> fp16 conversion ----------------
__global__ void cvtA_kernel(const float4* __restrict__ src) {
    const int n4 = N_TOK * H_DIM / 4;
    __half2* d = (__half2*)g_A;
    for (int i = blockIdx.x * blockDim.x + threadIdx.x; i < n4;
         i += gridDim.x * blockDim.x) {
        float4 v = src[i];
        d[2 * i]     = __floats2half2_rn(v.x, v.y);
        d[2 * i + 1] = __floats2half2_rn(v.z, v.w);
    }
}
__global__ void cvtB_kernel(const float4* __restrict__ src) {
    const int n4 = V_DIM * H_DIM / 4;
    __half2* d = (__half2*)g_B;
    for (int i = blockIdx.x * blockDim.x + threadIdx.x; i < n4;
         i += gridDim.x * blockDim.x) {
        float4 v = src[i];
        d[2 * i]     = __floats2half2_rn(v.x, v.y);
        d[2 * i + 1] = __floats2half2_rn(v.z, v.w);
    }
}

// ---------------- fused GEMM + partial CE ----------------
// grid = (NRB, NVB), blockIdx.x fastest so a wave shares each weight tile via L2.
// 256 threads = 8 warps in a 2 (m) x 4 (n) grid, warp tile 64x64. occupancy 2.
__global__ void __launch_bounds__(256, 2)
ce_gemm_kernel() {
    extern __shared__ char smem[];
    const int tid = threadIdx.x;
    const int wid = tid >> 5;
    const int l   = tid & 31;
    const int rb  = blockIdx.x;
    const int vb  = blockIdx.y;
    const int wm  = wid >> 2;     // 0..1
    const int wn  = wid & 3;      // 0..3
    const uint32_t sbase = smem_u32(smem);

    const __half* Ag = g_A + (size_t)rb * BM * H_DIM;
    const __half* Bg = g_B + (size_t)vb * BN * H_DIM;

    // cp.async: 1536 16B chunks per stage (A: 512, B: 1024), 6/thread.
    // smem row = 64B (4 chunks), swizzle: phys_chunk = c ^ ((row>>1)&3)
    const char* gsrc[6];
    uint32_t    sdst[6];
#pragma unroll
    for (int i = 0; i < 6; i++) {
        int q = tid + 256 * i;
        if (q < 512) {
            int r = q >> 2, c = q & 3;
            gsrc[i] = (const char*)(Ag + (size_t)r * H_DIM + c * 8);
            sdst[i] = (uint32_t)(r * 64 + ((c ^ ((r >> 1) & 3)) << 4));
        } else {
            int b = q - 512, r = b >> 2, c = b & 3;
            gsrc[i] = (const char*)(Bg + (size_t)r * H_DIM + c * 8);
            sdst[i] = (uint32_t)(8192 + r * 64 + ((c ^ ((r >> 1) & 3)) << 4));
        }
    }

    // ldmatrix lane-constant addressing
    const int rA = wm * 64 + (l & 15);
    const int cA = l >> 4;
    const int sA = (rA >> 1) & 3;
    const int nB = wn * 64 + ((l >> 4) << 3) + (l & 7);
    const int cB = (l >> 3) & 1;
    const int sB = (nB >> 1) & 3;

    // f16 accumulators: [mt][nt][slot]
    uint32_t acc[4][8][2];
#pragma unroll
    for (int mt = 0; mt < 4; mt++)
#pragma unroll
        for (int nt = 0; nt < 8; nt++) {
            acc[mt][nt][0] = 0u;
            acc[mt][nt][1] = 0u;
        }

    // prologue: stages 0..2
#pragma unroll
    for (int st = 0; st < 3; st++) {
        uint32_t b = sbase + st * STAGE_BYTES;
#pragma unroll
        for (int i = 0; i < 6; i++) CP_ASYNC16(b + sdst[i], gsrc[i] + (size_t)st * (BK * 2));
        CP_COMMIT();
    }

#pragma unroll 4
    for (int k = 0; k < KITERS; k++) {
        CP_WAIT2();          // stage k complete (<=2 younger groups pending)
        __syncthreads();
        if (k + 3 < KITERS) {
            uint32_t b = sbase + ((k + 3) % NSTAGE) * STAGE_BYTES;
#pragma unroll
            for (int i = 0; i < 6; i++)
                CP_ASYNC16(b + sdst[i], gsrc[i] + (size_t)(k + 3) * (BK * 2));
        }
        CP_COMMIT();   // unconditional: keeps wait_group accounting exact

        const uint32_t ab = sbase + (k % NSTAGE) * STAGE_BYTES;
#pragma unroll
        for (int ks = 0; ks < 2; ks++) {
            uint32_t a[4][4], b[4][4];
#pragma unroll
            for (int mt = 0; mt < 4; mt++)
                ldm_x4(a[mt][0], a[mt][1], a[mt][2], a[mt][3],
                       ab + (uint32_t)((rA + mt * 16) * 64 + (((ks * 2 + cA) ^ sA) << 4)));
#pragma unroll
            for (int p = 0; p < 4; p++)
                ldm_x4(b[p][0], b[p][1], b[p][2], b[p][3],
                       ab + 8192 + (uint32_t)((nB + p * 16) * 64 + (((ks * 2 + cB) ^ sB) << 4)));
#pragma unroll
            for (int mt = 0; mt < 4; mt++)
#pragma unroll
                for (int p = 0; p < 4; p++) {
                    mma16816h(acc[mt][2 * p],     a[mt], &b[p][0]);
                    mma16816h(acc[mt][2 * p + 1], a[mt], &b[p][2]);
                }
        }
    }

    // ---------------- epilogue ----------------
    __syncthreads();   // all tile reads done; smem reused for partials
    float* sm_m = (float*)smem;          // [4][128]
    float* sm_s = sm_m + 512;
    float* sm_t = sm_s + 512;
    const int* tgt_base = g_tgt + rb * BM;

#pragma unroll
    for (int mt = 0; mt < 4; mt++) {
#pragma unroll
        for (int slot = 0; slot < 2; slot++) {
            const int rloc = wm * 64 + mt * 16 + (l >> 2) + slot * 8;
            float x[8][2];
            float m = -1e30f;
#pragma unroll
            for (int nt = 0; nt < 8; nt++) {
                float2 f = __half22float2(*(__half2*)&acc[mt][nt][slot]);
                x[nt][0] = f.x;
                x[nt][1] = f.y;
                m = fmaxf(m, fmaxf(f.x, f.y));
            }
            m = fmaxf(m, __shfl_xor_sync(0xffffffffu, m, 1));
            m = fmaxf(m, __shfl_xor_sync(0xffffffffu, m, 2));
            const int tl = tgt_base[rloc] - vb * BN;
            float s = 0.0f, tv = 0.0f;
            const int colb = wn * 64 + (l & 3) * 2;
#pragma unroll
            for (int nt = 0; nt < 8; nt++) {
                s += __expf(x[nt][0] - m) + __expf(x[nt][1] - m);
                int c0 = colb + nt * 8;
                if (c0 == tl)     tv = x[nt][0];
                if (c0 + 1 == tl) tv = x[nt][1];
            }
            s  += __shfl_xor_sync(0xffffffffu, s, 1);
            s  += __shfl_xor_sync(0xffffffffu, s, 2);
            tv += __shfl_xor_sync(0xffffffffu, tv, 1);
            tv += __shfl_xor_sync(0xffffffffu, tv, 2);
            if ((l & 3) == 0) {
                sm_m[wn * 128 + rloc] = m;
                sm_s[wn * 128 + rloc] = s;
                sm_t[wn * 128 + rloc] = tv;
            }
        }
    }
    __syncthreads();
    if (tid < BM) {
        const int rg = rb * BM + tid;
        float m = sm_m[tid];
#pragma unroll
        for (int w = 1; w < 4; w++) m = fmaxf(m, sm_m[w * 128 + tid]);
        float s = 0.0f, tv = 0.0f;
#pragma unroll
        for (int w = 0; w < 4; w++) {
            s  += sm_s[w * 128 + tid] * __expf(sm_m[w * 128 + tid] - m);
            tv += sm_t[w * 128 + tid];
        }
        g_pmax[(size_t)vb * N_TOK + rg] = m;
        g_psum[(size_t)vb * N_TOK + rg] = s;
        int t = g_tgt[rg];
        int lo = vb * BN;
        if (t >= lo && t < lo + BN) g_tlog[rg] = tv;
    }
}

// ---------------- final logsumexp merge + mean ----------------
__global__ void reduce_kernel(float* __restrict__ out) {
    const int row = blockIdx.x * blockDim.x + threadIdx.x;
    float m = -1e30f;
    for (int i = 0; i < NVB; i++) m = fmaxf(m, g_pmax[(size_t)i * N_TOK + row]);
    float s = 0.0f;
    for (int i = 0; i < NVB; i++)
        s += g_psum[(size_t)i * N_TOK + row] * __expf(g_pmax[(size_t)i * N_TOK + row] - m);
    float nll = m + logf(s) - g_tlog[row];
#pragma unroll
    for (int o = 16; o; o >>= 1) nll += __shfl_xor_sync(0xffffffffu, nll, o);
    __shared__ float ws[8];
    if ((threadIdx.x & 31) == 0) ws[threadIdx.x >> 5] = nll;
    __syncthreads();
    if (threadIdx.x < 8) {
        float v = ws[threadIdx.x];
#pragma unroll
        for (int o = 4; o; o >>= 1) v += __shfl_xor_sync(0xffu, v, o);
        if (threadIdx.x == 0) atomicAdd(out, v / (float)N_TOK);
    }
}

// ---------------- launch ----------------
extern "C" void kernel_launch(void* const* d_in, const int* in_sizes, int n_in,
                              void* d_out, int out_size) {
    const float* input = (const float*)d_in[0];
    const float* weight = (const float*)d_in[1];
    const int* target32 = (const int*)d_in[2];
    float* out = (float*)d_out;

    cudaFuncSetAttribute(ce_gemm_kernel, cudaFuncAttributeMaxDynamicSharedMemorySize,
                         SMEM_TOTAL);

    detect_kernel<<<1, 1024>>>(target32);
    normalize_tgt_kernel<<<N_TOK / 256, 256>>>(target32);
    cvtA_kernel<<<4096, 256>>>((const float4*)input);
    cvtB_kernel<<<8192, 256>>>((const float4*)weight);
    cudaMemsetAsync(d_out, 0, sizeof(float));
    ce_gemm_kernel<<<dim3(NRB, NVB), 256, SMEM_TOTAL>>>();
    reduce_kernel<<<N_TOK / 256, 256>>>(out);
}

// round 9
// speedup vs baseline: 3.4107x; 1.0911x over previous
#include <cuda_runtime.h>
#include <cuda_fp16.h>
#include <cstdint>

// Problem dims
#define N_TOK 8192
#define H_DIM 4096
#define V_DIM 32000
// Tiling
#define BM 128
#define BN 256
#define BK 64                 // halfs per K-iter = 128 bytes per row
#define KITERS (H_DIM / BK)   // 64
#define NVB (V_DIM / BN)      // 125
#define NRB (N_TOK / BM)      // 64
#define STAGE_BYTES 49152     // A 16KB + B 32KB
#define SMEM_TOTAL (STAGE_BYTES * 2)   // 98304

// Scratch (static __device__ arrays: allocation-free per harness rules)
__device__ __half g_A[(size_t)N_TOK * H_DIM];     // 64 MB
__device__ __half g_B[(size_t)V_DIM * H_DIM];     // 256 MB
__device__ float g_pmax[(size_t)NVB * N_TOK];
__device__ float g_psum[(size_t)NVB * N_TOK];
__device__ float g_tlog[N_TOK];
__device__ int   g_tgt[N_TOK];
__device__ int   g_is64;

// ---------------- helpers ----------------
__device__ __forceinline__ uint32_t smem_u32(const void* p) {
    return (uint32_t)__cvta_generic_to_shared(p);
}
#define CP_ASYNC16(dst, src) \
    asm volatile("cp.async.cg.shared.global [%0], [%1], 16;" :: "r"(dst), "l"(src))
#define CP_COMMIT() asm volatile("cp.async.commit_group;" ::: "memory")
#define CP_WAIT0()  asm volatile("cp.async.wait_group 0;" ::: "memory")

__device__ __forceinline__ void ldm_x4(uint32_t& r0, uint32_t& r1, uint32_t& r2,
                                       uint32_t& r3, uint32_t addr) {
    asm volatile("ldmatrix.sync.aligned.m8n8.x4.shared.b16 {%0,%1,%2,%3}, [%4];"
                 : "=r"(r0), "=r"(r1), "=r"(r2), "=r"(r3) : "r"(addr));
}
// fp16 MMA with fp16 accumulate (2 acc regs -> enables occupancy 2)
__device__ __forceinline__ void mma16816h(uint32_t* c, const uint32_t* a, const uint32_t* b) {
    asm volatile(
        "mma.sync.aligned.m16n8k16.row.col.f16.f16.f16.f16 "
        "{%0,%1}, {%2,%3,%4,%5}, {%6,%7}, {%0,%1};"
        : "+r"(c[0]), "+r"(c[1])
        : "r"(a[0]), "r"(a[1]), "r"(a[2]), "r"(a[3]), "r"(b[0]), "r"(b[1]));
}

// ---------------- target dtype sniffing + normalization ----------------
__global__ void detect_kernel(const int* __restrict__ t32) {
    __shared__ int flag;
    if (threadIdx.x == 0) flag = 0;
    __syncthreads();
    int local = 0;
    for (int i = threadIdx.x; i < N_TOK / 2; i += blockDim.x)
        local |= t32[2 * i + 1];
    if (local) atomicOr(&flag, 1);
    __syncthreads();
    if (threadIdx.x == 0) g_is64 = (flag == 0) ? 1 : 0;
}
__global__ void normalize_tgt_kernel(const int* __restrict__ t32) {
    const int i = blockIdx.x * blockDim.x + threadIdx.x;
    g_tgt[i] = g_is64 ? t32[2 * i] : t32[i];
}

// ---------------- fp32 -> fp16 conversion ----------------
__global__ void cvtA_kernel(const float4* __restrict__ src) {
    const int n4 = N_TOK * H_DIM / 4;
    __half2* d = (__half2*)g_A;
    for (int i = blockIdx.x * blockDim.x + threadIdx.x; i < n4;
         i += gridDim.x * blockDim.x) {
        float4 v = src[i];
        d[2 * i]     = __floats2half2_rn(v.x, v.y);
        d[2 * i + 1] = __floats2half2_rn(v.z, v.w);
    }
}
__global__ void cvtB_kernel(const float4* __restrict__ src) {
    const int n4 = V_DIM * H_DIM / 4;
    __half2* d = (__half2*)g_B;
    for (int i = blockIdx.x * blockDim.x + threadIdx.x; i < n4;
         i += gridDim.x * blockDim.x) {
        float4 v = src[i];
        d[2 * i]     = __floats2half2_rn(v.x, v.y);
        d[2 * i + 1] = __floats2half2_rn(v.z, v.w);
    }
}

// ---------------- fused GEMM + partial CE ----------------
// grid = (NRB, NVB), blockIdx.x fastest so a wave shares each weight tile via L2.
// 256 threads = 8 warps in a 2 (m) x 4 (n) grid, warp tile 64x64. occupancy 2.
// 2-stage double buffer, BK=64: issue(k+1) -> compute(k) -> wait+sync. 64 barriers.
__global__ void __launch_bounds__(256, 2)
ce_gemm_kernel() {
    extern __shared__ char smem[];
    const int tid = threadIdx.x;
    const int wid = tid >> 5;
    const int l   = tid & 31;
    const int rb  = blockIdx.x;
    const int vb  = blockIdx.y;
    const int wm  = wid >> 2;     // 0..1
    const int wn  = wid & 3;      // 0..3
    const uint32_t sbase = smem_u32(smem);

    const __half* Ag = g_A + (size_t)rb * BM * H_DIM;
    const __half* Bg = g_B + (size_t)vb * BN * H_DIM;

    // cp.async: 3072 16B chunks/stage (A 1024, B 2048), 12/thread via 2 bases.
    // rows: r = tid>>3 (+32 per i), chunk c = tid&7. phys chunk = c ^ (r&7).
    const char* gA = (const char*)(Ag + (size_t)(tid >> 3) * H_DIM + (tid & 7) * 8);
    const char* gB = (const char*)(Bg + (size_t)(tid >> 3) * H_DIM + (tid & 7) * 8);
    const uint32_t dA = (uint32_t)((tid >> 3) * 128 + ((((tid & 7)) ^ ((tid >> 3) & 7)) << 4));
    const uint32_t dB = 16384 + dA;

    // ldmatrix lane-constant addressing (128B rows, swizzle selector = row&7)
    const int rA = wm * 64 + (l & 15);
    const int cA = l >> 4;
    const int sA = rA & 7;
    const int nB = wn * 64 + ((l >> 4) << 3) + (l & 7);
    const int cB = (l >> 3) & 1;
    const int sB = nB & 7;

    // f16 accumulators: [mt][nt][slot]
    uint32_t acc[4][8][2];
#pragma unroll
    for (int mt = 0; mt < 4; mt++)
#pragma unroll
        for (int nt = 0; nt < 8; nt++) {
            acc[mt][nt][0] = 0u;
            acc[mt][nt][1] = 0u;
        }

    // prologue: stage 0
    {
#pragma unroll
        for (int i = 0; i < 4; i++)
            CP_ASYNC16(sbase + dA + i * 4096, gA + (size_t)i * 32 * H_DIM * 2);
#pragma unroll
        for (int i = 0; i < 8; i++)
            CP_ASYNC16(sbase + dB + i * 4096, gB + (size_t)i * 32 * H_DIM * 2);
        CP_COMMIT();
        CP_WAIT0();
        __syncthreads();
    }

#pragma unroll 2
    for (int k = 0; k < KITERS; k++) {
        // issue stage k+1 into the other buffer (its old contents were read at
        // iter k-1; barrier at end of iter k-1 protects the overwrite)
        if (k + 1 < KITERS) {
            const uint32_t sb = sbase + ((k + 1) & 1) * STAGE_BYTES;
            const size_t koff = (size_t)(k + 1) * 128;
#pragma unroll
            for (int i = 0; i < 4; i++)
                CP_ASYNC16(sb + dA + i * 4096, gA + (size_t)i * 32 * H_DIM * 2 + koff);
#pragma unroll
            for (int i = 0; i < 8; i++)
                CP_ASYNC16(sb + dB + i * 4096, gB + (size_t)i * 32 * H_DIM * 2 + koff);
        }
        CP_COMMIT();

        // compute stage k: 4 x k16 sub-blocks
        const uint32_t ab = sbase + (k & 1) * STAGE_BYTES;
#pragma unroll
        for (int ks = 0; ks < 4; ks++) {
            uint32_t a[4][4], b[4][4];
#pragma unroll
            for (int mt = 0; mt < 4; mt++)
                ldm_x4(a[mt][0], a[mt][1], a[mt][2], a[mt][3],
                       ab + (uint32_t)((rA + mt * 16) * 128 + (((ks * 2 + cA) ^ sA) << 4)));
#pragma unroll
            for (int p = 0; p < 4; p++)
                ldm_x4(b[p][0], b[p][1], b[p][2], b[p][3],
                       ab + 16384 + (uint32_t)((nB + p * 16) * 128 + (((ks * 2 + cB) ^ sB) << 4)));
#pragma unroll
            for (int mt = 0; mt < 4; mt++)
#pragma unroll
                for (int p = 0; p < 4; p++) {
                    mma16816h(acc[mt][2 * p],     a[mt], &b[p][0]);
                    mma16816h(acc[mt][2 * p + 1], a[mt], &b[p][2]);
                }
        }

        CP_WAIT0();
        __syncthreads();
    }

    // ---------------- epilogue ----------------
    float* sm_m = (float*)smem;          // [4][128]
    float* sm_s = sm_m + 512;
    float* sm_t = sm_s + 512;
    const int* tgt_base = g_tgt + rb * BM;

#pragma unroll
    for (int mt = 0; mt < 4; mt++) {
#pragma unroll
        for (int slot = 0; slot < 2; slot++) {
            const int rloc = wm * 64 + mt * 16 + (l >> 2) + slot * 8;
            float x[8][2];
            float m = -1e30f;
#pragma unroll
            for (int nt = 0; nt < 8; nt++) {
                float2 f = __half22float2(*(__half2*)&acc[mt][nt][slot]);
                x[nt][0] = f.x;
                x[nt][1] = f.y;
                m = fmaxf(m, fmaxf(f.x, f.y));
            }
            m = fmaxf(m, __shfl_xor_sync(0xffffffffu, m, 1));
            m = fmaxf(m, __shfl_xor_sync(0xffffffffu, m, 2));
            const int tl = tgt_base[rloc] - vb * BN;
            float s = 0.0f, tv = 0.0f;
            const int colb = wn * 64 + (l & 3) * 2;
#pragma unroll
            for (int nt = 0; nt < 8; nt++) {
                s += __expf(x[nt][0] - m) + __expf(x[nt][1] - m);
                int c0 = colb + nt * 8;
                if (c0 == tl)     tv = x[nt][0];
                if (c0 + 1 == tl) tv = x[nt][1];
            }
            s  += __shfl_xor_sync(0xffffffffu, s, 1);
            s  += __shfl_xor_sync(0xffffffffu, s, 2);
            tv += __shfl_xor_sync(0xffffffffu, tv, 1);
            tv += __shfl_xor_sync(0xffffffffu, tv, 2);
            if ((l & 3) == 0) {
                sm_m[wn * 128 + rloc] = m;
                sm_s[wn * 128 + rloc] = s;
                sm_t[wn * 128 + rloc] = tv;
            }
        }
    }
    __syncthreads();
    if (tid < BM) {
        const int rg = rb * BM + tid;
        float m = sm_m[tid];
#pragma unroll
        for (int w = 1; w < 4; w++) m = fmaxf(m, sm_m[w * 128 + tid]);
        float s = 0.0f, tv = 0.0f;
#pragma unroll
        for (int w = 0; w < 4; w++) {
            s  += sm_s[w * 128 + tid] * __expf(sm_m[w * 128 + tid] - m);
            tv += sm_t[w * 128 + tid];
        }
        g_pmax[(size_t)vb * N_TOK + rg] = m;
        g_psum[(size_t)vb * N_TOK + rg] = s;
        int t = g_tgt[rg];
        int lo = vb * BN;
        if (t >= lo && t < lo + BN) g_tlog[rg] = tv;
    }
}

// ---------------- final logsumexp merge + mean ----------------
__global__ void reduce_kernel(float* __restrict__ out) {
    const int row = blockIdx.x * blockDim.x + threadIdx.x;
    float m = -1e30f;
    for (int i = 0; i < NVB; i++) m = fmaxf(m, g_pmax[(size_t)i * N_TOK + row]);
    float s = 0.0f;
    for (int i = 0; i < NVB; i++)
        s += g_psum[(size_t)i * N_TOK + row] * __expf(g_pmax[(size_t)i * N_TOK + row] - m);
    float nll = m + logf(s) - g_tlog[row];
#pragma unroll
    for (int o = 16; o; o >>= 1) nll += __shfl_xor_sync(0xffffffffu, nll, o);
    __shared__ float ws[8];
    if ((threadIdx.x & 31) == 0) ws[threadIdx.x >> 5] = nll;
    __syncthreads();
    if (threadIdx.x < 8) {
        float v = ws[threadIdx.x];
#pragma unroll
        for (int o = 4; o; o >>= 1) v += __shfl_xor_sync(0xffu, v, o);
        if (threadIdx.x == 0) atomicAdd(out, v / (float)N_TOK);
    }
}

// ---------------- launch ----------------
extern "C" void kernel_launch(void* const* d_in, const int* in_sizes, int n_in,
                              void* d_out, int out_size) {
    const float* input = (const float*)d_in[0];
    const float* weight = (const float*)d_in[1];
    const int* target32 = (const int*)d_in[2];
    float* out = (float*)d_out;

    cudaFuncSetAttribute(ce_gemm_kernel, cudaFuncAttributeMaxDynamicSharedMemorySize,
                         SMEM_TOTAL);

    detect_kernel<<<1, 1024>>>(target32);
    normalize_tgt_kernel<<<N_TOK / 256, 256>>>(target32);
    cvtA_kernel<<<4096, 256>>>((const float4*)input);
    cvtB_kernel<<<8192, 256>>>((const float4*)weight);
    cudaMemsetAsync(d_out, 0, sizeof(float));
    ce_gemm_kernel<<<dim3(NRB, NVB), 256, SMEM_TOTAL>>>();
    reduce_kernel<<<N_TOK / 256, 256>>>(out);
}